// round 1
// baseline (speedup 1.0000x reference)
#include <cuda_runtime.h>
#include <cstdint>

#define N_NODES   50000
#define IN_C      16
#define OUT_C     16
#define POS_C     16
#define KOFF      8
#define TEMP      8.0f
#define TPB       256

// ---------------------------------------------------------------------------
// Kernel 1: out[n, o] = bias[o]   (output buffer is poisoned; also folds bias)
// ---------------------------------------------------------------------------
__global__ void init_out_kernel(float* __restrict__ out,
                                const float* __restrict__ bias,
                                int total) {
    int idx = blockIdx.x * blockDim.x + threadIdx.x;
    if (idx < total) {
        out[idx] = bias[idx & (OUT_C - 1)];
    }
}

// ---------------------------------------------------------------------------
// Kernel 2: one thread per edge.
//   d = pos[col] - pos[row]
//   sim_k = -||d - offset_k|| * TEMP   (via d2 + o2 - 2 d.o)
//   alpha = softmax(sim)
//   msg_o = edge_attr * sum_k alpha_k * (W_k[o,:] . x[col])
//   red.global.add.v4 into out[row]
// ---------------------------------------------------------------------------
__global__ __launch_bounds__(TPB)
void genconv_edge_kernel(const float* __restrict__ x,
                         const float* __restrict__ pos,
                         const int*   __restrict__ ei,
                         const float* __restrict__ ea,
                         const float* __restrict__ offset,
                         const float* __restrict__ weight,
                         float* __restrict__ out,
                         int E) {
    __shared__ float s_off[KOFF * POS_C];    // [k][p]
    __shared__ float s_o2[KOFF];
    __shared__ __align__(16) float s_w[KOFF * OUT_C * IN_C];  // [k][o][i]

    int tid = threadIdx.x;
    // stage offsets + weights into shared
    for (int i = tid; i < KOFF * POS_C; i += TPB) s_off[i] = offset[i];
    for (int i = tid; i < KOFF * OUT_C * IN_C; i += TPB) s_w[i] = weight[i];
    __syncthreads();
    if (tid < KOFF) {
        float s = 0.f;
        #pragma unroll
        for (int p = 0; p < POS_C; p++) {
            float v = s_off[tid * POS_C + p];
            s += v * v;
        }
        s_o2[tid] = s;
    }
    __syncthreads();

    int e = blockIdx.x * TPB + tid;
    if (e >= E) return;

    int r = ei[e];
    int c = ei[E + e];

    // ---- d = pos[c] - pos[r], d2 = ||d||^2 ----
    const float4* pr = reinterpret_cast<const float4*>(pos + (size_t)r * POS_C);
    const float4* pc = reinterpret_cast<const float4*>(pos + (size_t)c * POS_C);
    float d[POS_C];
    float d2 = 0.f;
    #pragma unroll
    for (int j = 0; j < 4; j++) {
        float4 a = pc[j];
        float4 b = pr[j];
        d[4*j+0] = a.x - b.x;
        d[4*j+1] = a.y - b.y;
        d[4*j+2] = a.z - b.z;
        d[4*j+3] = a.w - b.w;
    }
    #pragma unroll
    for (int p = 0; p < POS_C; p++) d2 += d[p] * d[p];

    // ---- logits = -TEMP * sqrt(max(d2 + o2 - 2 d.o, 0)) ----
    float logit[KOFF];
    float m = -1e30f;
    #pragma unroll
    for (int k = 0; k < KOFF; k++) {
        float dot = 0.f;
        #pragma unroll
        for (int p = 0; p < POS_C; p++) dot += d[p] * s_off[k * POS_C + p];
        float sq = fmaxf(d2 + s_o2[k] - 2.0f * dot, 0.0f);
        float l = -TEMP * sqrtf(sq);
        logit[k] = l;
        m = fmaxf(m, l);
    }

    // ---- softmax (edge_attr folded into the normalizer) ----
    float al[KOFF];
    float asum = 0.f;
    #pragma unroll
    for (int k = 0; k < KOFF; k++) {
        float v = __expf(logit[k] - m);
        al[k] = v;
        asum += v;
    }
    float inv = ea[e] / asum;

    // ---- x[col] ----
    const float4* xc = reinterpret_cast<const float4*>(x + (size_t)c * IN_C);
    float xr[IN_C];
    #pragma unroll
    for (int j = 0; j < 4; j++) {
        float4 v = xc[j];
        xr[4*j+0] = v.x; xr[4*j+1] = v.y; xr[4*j+2] = v.z; xr[4*j+3] = v.w;
    }

    // ---- msg_o = sum_k a_k * (W_k[o,:] . xr) ----
    float msg[OUT_C];
    #pragma unroll
    for (int o = 0; o < OUT_C; o++) msg[o] = 0.f;

    #pragma unroll 1   // keep body I$-resident (~280 instrs instead of ~2.3k)
    for (int k = 0; k < KOFF; k++) {
        float a = al[k] * inv;
        const float4* wk = reinterpret_cast<const float4*>(s_w + k * OUT_C * IN_C);
        #pragma unroll
        for (int o = 0; o < OUT_C; o++) {
            float y = 0.f;
            #pragma unroll
            for (int i4 = 0; i4 < 4; i4++) {
                float4 w = wk[o * 4 + i4];   // uniform address -> LDS broadcast
                y += w.x * xr[4*i4+0];
                y += w.y * xr[4*i4+1];
                y += w.z * xr[4*i4+2];
                y += w.w * xr[4*i4+3];
            }
            msg[o] = fmaf(a, y, msg[o]);
        }
    }

    // ---- vectorized scatter-add: 4x red.global.add.v4.f32 ----
    float* dst = out + (size_t)r * OUT_C;
    #pragma unroll
    for (int j = 0; j < 4; j++) {
        asm volatile("red.global.add.v4.f32 [%0], {%1, %2, %3, %4};"
                     :: "l"(dst + 4 * j),
                        "f"(msg[4*j+0]), "f"(msg[4*j+1]),
                        "f"(msg[4*j+2]), "f"(msg[4*j+3])
                     : "memory");
    }
}

// ---------------------------------------------------------------------------
// Launch. Input order (metadata): x, pos, edge_index, edge_attr, offset,
// weight, bias. Output: float32 [N, OUT_C].
// ---------------------------------------------------------------------------
extern "C" void kernel_launch(void* const* d_in, const int* in_sizes, int n_in,
                              void* d_out, int out_size) {
    const float* x      = (const float*)d_in[0];
    const float* pos    = (const float*)d_in[1];
    const int*   ei     = (const int*)  d_in[2];
    const float* ea     = (const float*)d_in[3];
    const float* offset = (const float*)d_in[4];
    const float* weight = (const float*)d_in[5];
    const float* bias   = (const float*)d_in[6];
    float* out = (float*)d_out;

    int E = in_sizes[3];          // edge_attr has E elements
    int total_out = out_size;     // N * OUT_C

    int init_blocks = (total_out + TPB - 1) / TPB;
    init_out_kernel<<<init_blocks, TPB>>>(out, bias, total_out);

    int edge_blocks = (E + TPB - 1) / TPB;
    genconv_edge_kernel<<<edge_blocks, TPB>>>(x, pos, ei, ea, offset, weight,
                                              out, E);
}

// round 3
// speedup vs baseline: 1.1012x; 1.1012x over previous
#include <cuda_runtime.h>
#include <cstdint>

#define IN_C      16
#define OUT_C     16
#define POS_C     16
#define KOFF      8
#define TEMP      8.0f
#define TPB       256
#define EPB       (2 * TPB)    // edges per block

// ---------------------------------------------------------------------------
// Kernel 1: out[n, o] = bias[o]
// ---------------------------------------------------------------------------
__global__ void init_out_kernel(float* __restrict__ out,
                                const float* __restrict__ bias,
                                int total) {
    int idx = blockIdx.x * blockDim.x + threadIdx.x;
    if (idx < total) {
        out[idx] = bias[idx & (OUT_C - 1)];
    }
}

// packed fp32x2 FMA: y = w*xv + y   (sm_100+)
#define PKFMA(y, w, xv) \
    asm("fma.rn.f32x2 %0, %1, %2, %0;" : "+l"(y) : "l"(w), "l"(xv))

// ---------------------------------------------------------------------------
// Stage A (per edge): gather pos, logits, softmax, gather x (packed pairs).
// On exit: r = dest row, a[k] = alpha_k * edge_attr / sum, xp[8] = packed x.
// If !valid, a[] is all zero (msg becomes 0) and e is clamped.
// ---------------------------------------------------------------------------
__device__ __forceinline__ void stage_a(int e, int valid, int E,
                                        const float* __restrict__ x,
                                        const float* __restrict__ pos,
                                        const int* __restrict__ ei,
                                        const float* __restrict__ ea,
                                        const float* __restrict__ s_off,
                                        const float* __restrict__ s_o2,
                                        int& r, float* a,
                                        unsigned long long* xp) {
    r = ei[e];
    int c = ei[E + e];

    const float4* pr = reinterpret_cast<const float4*>(pos + (size_t)r * POS_C);
    const float4* pc = reinterpret_cast<const float4*>(pos + (size_t)c * POS_C);
    float d[POS_C];
    float d2 = 0.f;
#pragma unroll
    for (int j = 0; j < 4; j++) {
        float4 av = pc[j];
        float4 bv = pr[j];
        d[4 * j + 0] = av.x - bv.x;
        d[4 * j + 1] = av.y - bv.y;
        d[4 * j + 2] = av.z - bv.z;
        d[4 * j + 3] = av.w - bv.w;
    }
#pragma unroll
    for (int p = 0; p < POS_C; p++) d2 += d[p] * d[p];

    float logit[KOFF];
    float m = -1e30f;
#pragma unroll
    for (int k = 0; k < KOFF; k++) {
        float dot = 0.f;
#pragma unroll
        for (int p = 0; p < POS_C; p++) dot += d[p] * s_off[k * POS_C + p];
        float sq = fmaxf(d2 + s_o2[k] - 2.0f * dot, 0.0f);
        float l = -TEMP * sqrtf(sq);
        logit[k] = l;
        m = fmaxf(m, l);
    }

    float asum = 0.f;
#pragma unroll
    for (int k = 0; k < KOFF; k++) {
        float v = __expf(logit[k] - m);
        a[k] = v;
        asum += v;
    }
    float inv = valid ? (ea[e] / asum) : 0.0f;
#pragma unroll
    for (int k = 0; k < KOFF; k++) a[k] *= inv;

    const ulonglong2* xc = reinterpret_cast<const ulonglong2*>(x + (size_t)c * IN_C);
#pragma unroll
    for (int j = 0; j < 4; j++) {
        ulonglong2 v = xc[j];
        xp[2 * j + 0] = v.x;
        xp[2 * j + 1] = v.y;
    }
}

// ---------------------------------------------------------------------------
// Kernel 2: two edges per thread; shared-weight LDS amortized across both,
// inner products in packed f32x2.
// ---------------------------------------------------------------------------
__global__ __launch_bounds__(TPB)
void genconv_edge_kernel(const float* __restrict__ x,
                         const float* __restrict__ pos,
                         const int*   __restrict__ ei,
                         const float* __restrict__ ea,
                         const float* __restrict__ offset,
                         const float* __restrict__ weight,
                         float* __restrict__ out,
                         int E) {
    __shared__ float s_off[KOFF * POS_C];
    __shared__ float s_o2[KOFF];
    __shared__ __align__(16) float s_w[KOFF * OUT_C * IN_C];  // [k][o][i]

    int tid = threadIdx.x;
    for (int i = tid; i < KOFF * POS_C; i += TPB) s_off[i] = offset[i];
    for (int i = tid; i < KOFF * OUT_C * IN_C; i += TPB) s_w[i] = weight[i];
    __syncthreads();
    if (tid < KOFF) {
        float s = 0.f;
#pragma unroll
        for (int p = 0; p < POS_C; p++) {
            float v = s_off[tid * POS_C + p];
            s += v * v;
        }
        s_o2[tid] = s;
    }
    __syncthreads();

    int e0 = blockIdx.x * EPB + tid;
    int e1 = e0 + TPB;
    if (e0 >= E) return;
    int v1 = (e1 < E);
    int e1c = v1 ? e1 : e0;

    int r0, r1;
    float a0[KOFF], a1[KOFF];
    unsigned long long xp0[8], xp1[8];
    stage_a(e0, 1, E, x, pos, ei, ea, s_off, s_o2, r0, a0, xp0);
    stage_a(e1c, v1, E, x, pos, ei, ea, s_off, s_o2, r1, a1, xp1);

    float msg0[OUT_C], msg1[OUT_C];
#pragma unroll
    for (int o = 0; o < OUT_C; o++) { msg0[o] = 0.f; msg1[o] = 0.f; }

#pragma unroll 1   // keep I$-resident: body ~450 instrs
    for (int k = 0; k < KOFF; k++) {
        float a0k = a0[k];
        float a1k = a1[k];
        const ulonglong2* wk =
            reinterpret_cast<const ulonglong2*>(s_w + k * OUT_C * IN_C);
#pragma unroll
        for (int o = 0; o < OUT_C; o++) {
            // W_k[o, 0:16] = 4 x ulonglong2 (LDS.128 each) = 8 packed pairs
            ulonglong2 wA = wk[o * 4 + 0];
            ulonglong2 wB = wk[o * 4 + 1];
            ulonglong2 wC = wk[o * 4 + 2];
            ulonglong2 wD = wk[o * 4 + 3];

            unsigned long long y0 = 0ull, y1 = 0ull;  // packed (0.0f, 0.0f)
            PKFMA(y0, wA.x, xp0[0]); PKFMA(y1, wA.x, xp1[0]);
            PKFMA(y0, wA.y, xp0[1]); PKFMA(y1, wA.y, xp1[1]);
            PKFMA(y0, wB.x, xp0[2]); PKFMA(y1, wB.x, xp1[2]);
            PKFMA(y0, wB.y, xp0[3]); PKFMA(y1, wB.y, xp1[3]);
            PKFMA(y0, wC.x, xp0[4]); PKFMA(y1, wC.x, xp1[4]);
            PKFMA(y0, wC.y, xp0[5]); PKFMA(y1, wC.y, xp1[5]);
            PKFMA(y0, wD.x, xp0[6]); PKFMA(y1, wD.x, xp1[6]);
            PKFMA(y0, wD.y, xp0[7]); PKFMA(y1, wD.y, xp1[7]);

            float lo0, hi0, lo1, hi1;
            asm("mov.b64 {%0, %1}, %2;" : "=f"(lo0), "=f"(hi0) : "l"(y0));
            asm("mov.b64 {%0, %1}, %2;" : "=f"(lo1), "=f"(hi1) : "l"(y1));
            msg0[o] = fmaf(a0k, lo0 + hi0, msg0[o]);
            msg1[o] = fmaf(a1k, lo1 + hi1, msg1[o]);
        }
    }

    // ---- scatter-add ----
    float* dst0 = out + (size_t)r0 * OUT_C;
#pragma unroll
    for (int j = 0; j < 4; j++) {
        asm volatile("red.global.add.v4.f32 [%0], {%1, %2, %3, %4};"
                     :: "l"(dst0 + 4 * j),
                        "f"(msg0[4*j+0]), "f"(msg0[4*j+1]),
                        "f"(msg0[4*j+2]), "f"(msg0[4*j+3])
                     : "memory");
    }
    if (v1) {
        float* dst1 = out + (size_t)r1 * OUT_C;
#pragma unroll
        for (int j = 0; j < 4; j++) {
            asm volatile("red.global.add.v4.f32 [%0], {%1, %2, %3, %4};"
                         :: "l"(dst1 + 4 * j),
                            "f"(msg1[4*j+0]), "f"(msg1[4*j+1]),
                            "f"(msg1[4*j+2]), "f"(msg1[4*j+3])
                         : "memory");
        }
    }
}

// ---------------------------------------------------------------------------
extern "C" void kernel_launch(void* const* d_in, const int* in_sizes, int n_in,
                              void* d_out, int out_size) {
    const float* x      = (const float*)d_in[0];
    const float* pos    = (const float*)d_in[1];
    const int*   ei     = (const int*)  d_in[2];
    const float* ea     = (const float*)d_in[3];
    const float* offset = (const float*)d_in[4];
    const float* weight = (const float*)d_in[5];
    const float* bias   = (const float*)d_in[6];
    float* out = (float*)d_out;

    int E = in_sizes[3];
    int total_out = out_size;

    int init_blocks = (total_out + TPB - 1) / TPB;
    init_out_kernel<<<init_blocks, TPB>>>(out, bias, total_out);

    int edge_blocks = (E + EPB - 1) / EPB;
    genconv_edge_kernel<<<edge_blocks, TPB>>>(x, pos, ei, ea, offset, weight,
                                              out, E);
}

// round 4
// speedup vs baseline: 1.2764x; 1.1591x over previous
#include <cuda_runtime.h>
#include <cstdint>

#define IN_C   16
#define OUT_C  16
#define POS_C  16
#define KOFF   8
#define TEMP   8.0f
#define TPB    256
#define WPB    8           // warps per block
#define TILE   32          // edges per warp-tile

// ---------------------------------------------------------------------------
// Kernel 1: out[n, o] = bias[o]
// ---------------------------------------------------------------------------
__global__ void init_out_kernel(float* __restrict__ out,
                                const float* __restrict__ bias,
                                int total) {
    int idx = blockIdx.x * blockDim.x + threadIdx.x;
    if (idx < total) out[idx] = bias[idx & (OUT_C - 1)];
}

// packed fp32x2 FMA: y += w * xv  (sm_100+)
#define PKFMA(y, w, xv) \
    asm("fma.rn.f32x2 %0, %1, %2, %0;" : "+l"(y) : "l"(w), "l"(xv))

__device__ __forceinline__ float upk_sum(unsigned long long v) {
    float lo, hi;
    asm("mov.b64 {%0, %1}, %2;" : "=f"(lo), "=f"(hi) : "l"(v));
    return lo + hi;
}

// ---------------------------------------------------------------------------
// Warp-cooperative kernel.
// Lane l permanently owns output channel o = l & 15 and the 4 offsets
// k = 4*(l>>4) .. +3, holding W[k][o][0:16] in registers (64 floats/lane).
// Each warp loops over 32-edge tiles:
//   Phase A: lane-per-edge softmax + gathers -> per-warp SMEM (x, alpha, row)
//   Phase B: per edge, warp computes msg[o] via packed FMAs + shfl reduce
//   Scatter: batched red.global.add.v4 across all 32 lanes
// ---------------------------------------------------------------------------
__global__ __launch_bounds__(TPB, 2)
void genconv_coop_kernel(const float* __restrict__ x,
                         const float* __restrict__ pos,
                         const int*   __restrict__ ei,
                         const float* __restrict__ ea,
                         const float* __restrict__ offset,
                         const float* __restrict__ weight,
                         float* __restrict__ out,
                         int E, int nWarpsTotal) {
    __shared__ float s_off[KOFF * POS_C];
    __shared__ float s_o2[KOFF];
    // per-warp scratch
    __shared__ unsigned long long s_x[WPB][8 * TILE];   // [i2][e], 2KB/warp
    __shared__ float s_al[WPB][TILE * KOFF];            // [e][k],  1KB/warp
    __shared__ int   s_r [WPB][TILE];                   //          128B/warp
    __shared__ float s_m [WPB][TILE * OUT_C];           // [e][o],  2KB/warp

    const int tid  = threadIdx.x;
    const int lane = tid & 31;
    const int wrp  = tid >> 5;
    const int o    = lane & 15;
    const int kh   = lane >> 4;          // 0 -> k 0..3, 1 -> k 4..7

    for (int i = tid; i < KOFF * POS_C; i += TPB) s_off[i] = offset[i];
    __syncthreads();
    if (tid < KOFF) {
        float s = 0.f;
#pragma unroll
        for (int p = 0; p < POS_C; p++) {
            float v = s_off[tid * POS_C + p];
            s += v * v;
        }
        s_o2[tid] = s;
    }
    __syncthreads();

    // ---- persistent weights: W[kh*4+j][o][i], i-pairs packed in u64 ----
    ulonglong2 wr[4][4];   // [j][q]: q-th 16B chunk = float pairs (4q,4q+1),(4q+2,4q+3)
#pragma unroll
    for (int j = 0; j < 4; j++) {
#pragma unroll
        for (int q = 0; q < 4; q++) {
            wr[j][q] = *reinterpret_cast<const ulonglong2*>(
                weight + ((kh * 4 + j) * (OUT_C * IN_C) + o * IN_C + q * 4));
        }
    }

    unsigned long long* xw = s_x[wrp];
    float*              aw = s_al[wrp];
    int*                rw = s_r[wrp];
    float*              mw = s_m[wrp];

    const int gwarp  = blockIdx.x * WPB + wrp;
    const int nTiles = (E + TILE - 1) / TILE;

    for (int t = gwarp; t < nTiles; t += nWarpsTotal) {
        // ================= Phase A: lane-per-edge =================
        int et = t * TILE + lane;
        int valid = (et < E);
        int e = valid ? et : 0;
        int r = ei[e];
        int c = ei[E + e];

        const float4* pr4 = reinterpret_cast<const float4*>(pos + (size_t)r * POS_C);
        const float4* pc4 = reinterpret_cast<const float4*>(pos + (size_t)c * POS_C);
        float d[POS_C];
        float d2 = 0.f;
#pragma unroll
        for (int j = 0; j < 4; j++) {
            float4 av = pc4[j];
            float4 bv = pr4[j];
            d[4*j+0] = av.x - bv.x; d[4*j+1] = av.y - bv.y;
            d[4*j+2] = av.z - bv.z; d[4*j+3] = av.w - bv.w;
        }
#pragma unroll
        for (int p = 0; p < POS_C; p++) d2 += d[p] * d[p];

        float logit[KOFF];
        float mx = -1e30f;
#pragma unroll
        for (int k = 0; k < KOFF; k++) {
            float dot = 0.f;
            const float4* ok4 = reinterpret_cast<const float4*>(s_off + k * POS_C);
#pragma unroll
            for (int j = 0; j < 4; j++) {
                float4 ov = ok4[j];
                dot += d[4*j+0]*ov.x + d[4*j+1]*ov.y + d[4*j+2]*ov.z + d[4*j+3]*ov.w;
            }
            float sq = fmaxf(d2 + s_o2[k] - 2.0f * dot, 0.0f);
            float l = -TEMP * sqrtf(sq);
            logit[k] = l;
            mx = fmaxf(mx, l);
        }
        float a[KOFF];
        float asum = 0.f;
#pragma unroll
        for (int k = 0; k < KOFF; k++) {
            float v = __expf(logit[k] - mx);
            a[k] = v;
            asum += v;
        }
        float inv = valid ? (ea[e] / asum) : 0.0f;

        rw[lane] = r;
        float4* aw4 = reinterpret_cast<float4*>(aw + lane * KOFF);
        aw4[0] = make_float4(a[0]*inv, a[1]*inv, a[2]*inv, a[3]*inv);
        aw4[1] = make_float4(a[4]*inv, a[5]*inv, a[6]*inv, a[7]*inv);

        // x[col] as 8 packed pairs, stored transposed [i2][lane] (conflict-free)
        const ulonglong2* xc2 = reinterpret_cast<const ulonglong2*>(x + (size_t)c * IN_C);
#pragma unroll
        for (int j = 0; j < 4; j++) {
            ulonglong2 v = xc2[j];
            xw[(2*j + 0) * TILE + lane] = v.x;
            xw[(2*j + 1) * TILE + lane] = v.y;
        }
        __syncwarp();

        // ================= Phase B: warp-per-edge =================
#pragma unroll 2
        for (int eb = 0; eb < TILE; eb++) {
            float4 a4 = *reinterpret_cast<const float4*>(aw + eb * KOFF + kh * 4);
            unsigned long long acc0 = 0ull, acc1 = 0ull, acc2 = 0ull, acc3 = 0ull;
#pragma unroll
            for (int q = 0; q < 4; q++) {
                unsigned long long xv0 = xw[(2*q + 0) * TILE + eb];
                unsigned long long xv1 = xw[(2*q + 1) * TILE + eb];
                PKFMA(acc0, wr[0][q].x, xv0); PKFMA(acc0, wr[0][q].y, xv1);
                PKFMA(acc1, wr[1][q].x, xv0); PKFMA(acc1, wr[1][q].y, xv1);
                PKFMA(acc2, wr[2][q].x, xv0); PKFMA(acc2, wr[2][q].y, xv1);
                PKFMA(acc3, wr[3][q].x, xv0); PKFMA(acc3, wr[3][q].y, xv1);
            }
            float part = a4.x * upk_sum(acc0);
            part = fmaf(a4.y, upk_sum(acc1), part);
            part = fmaf(a4.z, upk_sum(acc2), part);
            part = fmaf(a4.w, upk_sum(acc3), part);
            // combine kh=0 and kh=1 halves
            part += __shfl_xor_sync(0xffffffffu, part, 16);
            if (lane < 16) mw[eb * OUT_C + o] = part;
        }
        __syncwarp();

        // ================= Scatter: batched red.v4 =================
#pragma unroll
        for (int q = 0; q < 4; q++) {
            int idx = q * 32 + lane;          // 0..127 quads
            int eb  = idx >> 2;
            int qd  = idx & 3;
            int rr  = rw[eb];
            float4 v = *reinterpret_cast<const float4*>(mw + eb * OUT_C + qd * 4);
            float* dst = out + (size_t)rr * OUT_C + qd * 4;
            asm volatile("red.global.add.v4.f32 [%0], {%1, %2, %3, %4};"
                         :: "l"(dst), "f"(v.x), "f"(v.y), "f"(v.z), "f"(v.w)
                         : "memory");
        }
        __syncwarp();
    }
}

// ---------------------------------------------------------------------------
extern "C" void kernel_launch(void* const* d_in, const int* in_sizes, int n_in,
                              void* d_out, int out_size) {
    const float* x      = (const float*)d_in[0];
    const float* pos    = (const float*)d_in[1];
    const int*   ei     = (const int*)  d_in[2];
    const float* ea     = (const float*)d_in[3];
    const float* offset = (const float*)d_in[4];
    const float* weight = (const float*)d_in[5];
    const float* bias   = (const float*)d_in[6];
    float* out = (float*)d_out;

    int E = in_sizes[3];
    int total_out = out_size;

    int init_blocks = (total_out + TPB - 1) / TPB;
    init_out_kernel<<<init_blocks, TPB>>>(out, bias, total_out);

    const int blocks = 296;                      // 2 per SM on 148-SM B200
    const int nWarpsTotal = blocks * WPB;
    genconv_coop_kernel<<<blocks, TPB>>>(x, pos, ei, ea, offset, weight,
                                         out, E, nWarpsTotal);
}

// round 5
// speedup vs baseline: 1.4815x; 1.1607x over previous
#include <cuda_runtime.h>
#include <cstdint>

#define IN_C     16
#define OUT_C    16
#define POS_C    16
#define KOFF     8
#define TEMP     8.0f
#define TPB      128
#define WPB      4          // warps per block
#define TILE     32         // edges per warp-tile
#define DSTRIDE  20         // padded floats per edge in s_d (bank-conflict-free)

// ---------------------------------------------------------------------------
// Kernel 1: out[n, o] = bias[o]
// ---------------------------------------------------------------------------
__global__ void init_out_kernel(float* __restrict__ out,
                                const float* __restrict__ bias,
                                int total) {
    int idx = blockIdx.x * blockDim.x + threadIdx.x;
    if (idx < total) out[idx] = bias[idx & (OUT_C - 1)];
}

// packed fp32x2 FMA: y += w * xv  (sm_100+)
#define PKFMA(y, w, xv) \
    asm("fma.rn.f32x2 %0, %1, %2, %0;" : "+l"(y) : "l"(w), "l"(xv))

__device__ __forceinline__ float upk_sum(unsigned long long v) {
    float lo, hi;
    asm("mov.b64 {%0, %1}, %2;" : "=f"(lo), "=f"(hi) : "l"(v));
    return lo + hi;
}

// ---------------------------------------------------------------------------
// Warp-cooperative kernel, 3 phases per 32-edge tile:
//  Gather (4 lanes/edge): pos[r],pos[c],x[c] fetched in 16B chunks so each
//    LDG.128's 32 lanes touch only 8 cache lines (4x fewer L1 wavefronts).
//    d = pos[c]-pos[r] computed in-register, stored to SMEM (padded).
//  Softmax (lane/edge): d from SMEM -> logits -> alpha * ea / sum.
//  Phase B (warp/edge): persistent register weights, packed f32x2 FMAs,
//    shfl-combined k-halves, batched red.global.add.v4 scatter.
// ---------------------------------------------------------------------------
__global__ __launch_bounds__(TPB, 4)
void genconv_coop_kernel(const float* __restrict__ x,
                         const float* __restrict__ pos,
                         const int*   __restrict__ ei,
                         const float* __restrict__ ea,
                         const float* __restrict__ offset,
                         const float* __restrict__ weight,
                         float* __restrict__ out,
                         int E, int nWarpsTotal) {
    __shared__ float s_off[KOFF * POS_C];
    __shared__ float s_o2[KOFF];
    __shared__ float s_d[WPB][TILE * DSTRIDE];              // 2.5KB/warp
    __shared__ __align__(16) ulonglong2 s_x[WPB][TILE * 4]; // [eb*4+q], 2KB/warp
    __shared__ float s_al[WPB][TILE * KOFF];                // [eb][k], 1KB/warp
    __shared__ int   s_r [WPB][TILE];
    __shared__ float s_m [WPB][TILE * OUT_C];               // 2KB/warp

    const int tid  = threadIdx.x;
    const int lane = tid & 31;
    const int wrp  = tid >> 5;
    const int o    = lane & 15;
    const int kh   = lane >> 4;          // k-half: 0 -> k0..3, 1 -> k4..7

    for (int i = tid; i < KOFF * POS_C; i += TPB) s_off[i] = offset[i];
    __syncthreads();
    if (tid < KOFF) {
        float s = 0.f;
#pragma unroll
        for (int p = 0; p < POS_C; p++) {
            float v = s_off[tid * POS_C + p];
            s += v * v;
        }
        s_o2[tid] = s;
    }
    __syncthreads();

    // persistent weights: W[kh*4+j][o][i], i-pairs packed in u64
    ulonglong2 wr[4][4];
#pragma unroll
    for (int j = 0; j < 4; j++) {
#pragma unroll
        for (int q = 0; q < 4; q++) {
            wr[j][q] = *reinterpret_cast<const ulonglong2*>(
                weight + ((kh * 4 + j) * (OUT_C * IN_C) + o * IN_C + q * 4));
        }
    }

    float*      dw = s_d[wrp];
    ulonglong2* xw = s_x[wrp];
    float*      aw = s_al[wrp];
    int*        rw = s_r[wrp];
    float*      mw = s_m[wrp];

    const int gwarp  = blockIdx.x * WPB + wrp;
    const int nTiles = (E + TILE - 1) / TILE;

    for (int t = gwarp; t < nTiles; t += nWarpsTotal) {
        // ============ Gather phase: 4 lanes per edge, 4 passes ============
        const int ebg = lane >> 2;       // edge-in-pass
        const int q   = lane & 3;        // 16B chunk
#pragma unroll
        for (int p = 0; p < 4; p++) {
            int eb = p * 8 + ebg;
            int et = t * TILE + eb;
            int e  = min(et, E - 1);
            int r  = ei[e];
            int c  = ei[E + e];
            float4 av = *reinterpret_cast<const float4*>(
                pos + (size_t)c * POS_C + q * 4);
            float4 bv = *reinterpret_cast<const float4*>(
                pos + (size_t)r * POS_C + q * 4);
            float4 dq;
            dq.x = av.x - bv.x; dq.y = av.y - bv.y;
            dq.z = av.z - bv.z; dq.w = av.w - bv.w;
            *reinterpret_cast<float4*>(dw + eb * DSTRIDE + q * 4) = dq;
            xw[eb * 4 + q] = *reinterpret_cast<const ulonglong2*>(
                x + (size_t)c * IN_C + q * 4);
        }
        __syncwarp();

        // ============ Softmax phase: lane per edge ============
        {
            int et = t * TILE + lane;
            int valid = (et < E);
            int e = min(et, E - 1);

            float d[POS_C];
#pragma unroll
            for (int j = 0; j < 4; j++) {
                float4 v = *reinterpret_cast<const float4*>(
                    dw + lane * DSTRIDE + j * 4);
                d[4*j+0] = v.x; d[4*j+1] = v.y; d[4*j+2] = v.z; d[4*j+3] = v.w;
            }
            float d2 = 0.f;
#pragma unroll
            for (int p = 0; p < POS_C; p++) d2 += d[p] * d[p];

            float logit[KOFF];
            float mx = -1e30f;
#pragma unroll
            for (int k = 0; k < KOFF; k++) {
                float dot = 0.f;
                const float4* ok4 =
                    reinterpret_cast<const float4*>(s_off + k * POS_C);
#pragma unroll
                for (int j = 0; j < 4; j++) {
                    float4 ov = ok4[j];
                    dot += d[4*j+0]*ov.x + d[4*j+1]*ov.y
                         + d[4*j+2]*ov.z + d[4*j+3]*ov.w;
                }
                float sq = fmaxf(d2 + s_o2[k] - 2.0f * dot, 0.0f);
                float l = -TEMP * sqrtf(sq);
                logit[k] = l;
                mx = fmaxf(mx, l);
            }
            float a[KOFF];
            float asum = 0.f;
#pragma unroll
            for (int k = 0; k < KOFF; k++) {
                float v = __expf(logit[k] - mx);
                a[k] = v;
                asum += v;
            }
            float inv = valid ? (ea[e] / asum) : 0.0f;

            rw[lane] = ei[e];
            float4* aw4 = reinterpret_cast<float4*>(aw + lane * KOFF);
            aw4[0] = make_float4(a[0]*inv, a[1]*inv, a[2]*inv, a[3]*inv);
            aw4[1] = make_float4(a[4]*inv, a[5]*inv, a[6]*inv, a[7]*inv);
        }
        __syncwarp();

        // ============ Phase B: warp per edge ============
#pragma unroll 2
        for (int eb = 0; eb < TILE; eb++) {
            float4 a4 = *reinterpret_cast<const float4*>(aw + eb * KOFF + kh * 4);
            ulonglong2 xv0 = xw[eb * 4 + 0];
            ulonglong2 xv1 = xw[eb * 4 + 1];
            ulonglong2 xv2 = xw[eb * 4 + 2];
            ulonglong2 xv3 = xw[eb * 4 + 3];

            unsigned long long acc0 = 0ull, acc1 = 0ull, acc2 = 0ull, acc3 = 0ull;
            PKFMA(acc0, wr[0][0].x, xv0.x); PKFMA(acc0, wr[0][0].y, xv0.y);
            PKFMA(acc1, wr[1][0].x, xv0.x); PKFMA(acc1, wr[1][0].y, xv0.y);
            PKFMA(acc2, wr[2][0].x, xv0.x); PKFMA(acc2, wr[2][0].y, xv0.y);
            PKFMA(acc3, wr[3][0].x, xv0.x); PKFMA(acc3, wr[3][0].y, xv0.y);
            PKFMA(acc0, wr[0][1].x, xv1.x); PKFMA(acc0, wr[0][1].y, xv1.y);
            PKFMA(acc1, wr[1][1].x, xv1.x); PKFMA(acc1, wr[1][1].y, xv1.y);
            PKFMA(acc2, wr[2][1].x, xv1.x); PKFMA(acc2, wr[2][1].y, xv1.y);
            PKFMA(acc3, wr[3][1].x, xv1.x); PKFMA(acc3, wr[3][1].y, xv1.y);
            PKFMA(acc0, wr[0][2].x, xv2.x); PKFMA(acc0, wr[0][2].y, xv2.y);
            PKFMA(acc1, wr[1][2].x, xv2.x); PKFMA(acc1, wr[1][2].y, xv2.y);
            PKFMA(acc2, wr[2][2].x, xv2.x); PKFMA(acc2, wr[2][2].y, xv2.y);
            PKFMA(acc3, wr[3][2].x, xv2.x); PKFMA(acc3, wr[3][2].y, xv2.y);
            PKFMA(acc0, wr[0][3].x, xv3.x); PKFMA(acc0, wr[0][3].y, xv3.y);
            PKFMA(acc1, wr[1][3].x, xv3.x); PKFMA(acc1, wr[1][3].y, xv3.y);
            PKFMA(acc2, wr[2][3].x, xv3.x); PKFMA(acc2, wr[2][3].y, xv3.y);
            PKFMA(acc3, wr[3][3].x, xv3.x); PKFMA(acc3, wr[3][3].y, xv3.y);

            float part = a4.x * upk_sum(acc0);
            part = fmaf(a4.y, upk_sum(acc1), part);
            part = fmaf(a4.z, upk_sum(acc2), part);
            part = fmaf(a4.w, upk_sum(acc3), part);
            part += __shfl_xor_sync(0xffffffffu, part, 16);
            if (lane < 16) mw[eb * OUT_C + o] = part;
        }
        __syncwarp();

        // ============ Scatter: batched red.v4 ============
#pragma unroll
        for (int qq = 0; qq < 4; qq++) {
            int idx = qq * 32 + lane;        // 0..127 quads
            int eb  = idx >> 2;
            int qd  = idx & 3;
            int rr  = rw[eb];
            float4 v = *reinterpret_cast<const float4*>(mw + eb * OUT_C + qd * 4);
            float* dst = out + (size_t)rr * OUT_C + qd * 4;
            asm volatile("red.global.add.v4.f32 [%0], {%1, %2, %3, %4};"
                         :: "l"(dst), "f"(v.x), "f"(v.y), "f"(v.z), "f"(v.w)
                         : "memory");
        }
        __syncwarp();
    }
}

// ---------------------------------------------------------------------------
extern "C" void kernel_launch(void* const* d_in, const int* in_sizes, int n_in,
                              void* d_out, int out_size) {
    const float* x      = (const float*)d_in[0];
    const float* pos    = (const float*)d_in[1];
    const int*   ei     = (const int*)  d_in[2];
    const float* ea     = (const float*)d_in[3];
    const float* offset = (const float*)d_in[4];
    const float* weight = (const float*)d_in[5];
    const float* bias   = (const float*)d_in[6];
    float* out = (float*)d_out;

    int E = in_sizes[3];
    int total_out = out_size;

    int init_blocks = (total_out + 255) / 256;
    init_out_kernel<<<init_blocks, 256>>>(out, bias, total_out);

    const int blocks = 592;                 // 4 per SM on 148-SM B200
    const int nWarpsTotal = blocks * WPB;
    genconv_coop_kernel<<<blocks, TPB>>>(x, pos, ei, ea, offset, weight,
                                         out, E, nWarpsTotal);
}